// round 2
// baseline (speedup 1.0000x reference)
#include <cuda_runtime.h>

// Problem constants (fixed shapes from setup_inputs)
#define NB 4
#define NC 64
#define NH 64
#define NW 64
#define NHW 4096

// ---------------- device scratch (no allocations allowed) ----------------
__device__ __align__(16) float g_xT[NB*NHW*NC];      // x in NHWC
__device__ __align__(16) float g_attn0[NB*NC*NHW];   // attn after deform0, NCHW
__device__ __align__(16) float g_attn0T[NB*NHW*NC];  // attn after deform0, NHWC
__device__ __align__(16) float g_off0[NB*50*NHW];
__device__ __align__(16) float g_off1[NB*98*NHW];
__device__ __align__(16) float g_wT0[576*52];        // [c*9+tap][o] padded 50->52
__device__ __align__(16) float g_wT1[576*100 + 64];  // padded 98->100 (+guard)
__device__ __align__(16) float g_wdw0T[25*64];       // [k][c]
__device__ __align__(16) float g_wdw1T[49*64];       // [k][c]
__device__ __align__(16) float g_wpwT[64*64];        // [c][o]

// ---------------- weight repack ----------------
__global__ void prep_kernel(const float* __restrict__ w_off0, const float* __restrict__ w_off1,
                            const float* __restrict__ w_dw0,  const float* __restrict__ w_dw1,
                            const float* __restrict__ w_pw) {
    int i = blockIdx.x * 256 + threadIdx.x;
    if (i < 576*52) {
        int r = i / 52, o = i % 52, c = r / 9, t = r % 9;
        g_wT0[i] = (o < 50) ? w_off0[(o*64 + c)*9 + t] : 0.f;
    }
    if (i < 576*100) {
        int r = i / 100, o = i % 100, c = r / 9, t = r % 9;
        g_wT1[i] = (o < 98) ? w_off1[(o*64 + c)*9 + t] : 0.f;
    }
    if (i < 25*64) { int k = i >> 6, c = i & 63; g_wdw0T[i] = w_dw0[c*25 + k]; }
    if (i < 49*64) { int k = i >> 6, c = i & 63; g_wdw1T[i] = w_dw1[c*49 + k]; }
    if (i < 4096)  { int c = i >> 6, o = i & 63; g_wpwT[i]  = w_pw[o*64 + c]; }
}

// ---------------- NCHW -> NHWC transpose of x ----------------
__global__ void transpose_kernel(const float* __restrict__ x) {
    __shared__ float sm[64*65];
    int bh = blockIdx.x;
    int b = bh >> 6, h = bh & 63;
    int tid = threadIdx.x;
    for (int i = tid; i < 4096; i += 256) {
        int c = i >> 6, w = i & 63;
        sm[c*65 + w] = x[((b*64 + c)*64 + h)*64 + w];
    }
    __syncthreads();
    for (int i = tid; i < 4096; i += 256) {
        int w = i >> 6, c = i & 63;
        g_xT[(b*4096 + h*64 + w)*64 + c] = sm[c*65 + w];
    }
}

// ---------------- 3x3 offset conv (pad=1), register tiled 4o x 4w ----------------
// Static smem: two half-channel passes of [3][32][68] = 26112 bytes each.
// which==0: in = x param, wT=g_wT0, O=50, OPAD=52,  out=g_off0
// which==1: in = g_attn0, wT=g_wT1, O=98, OPAD=100, out=g_off1
__global__ void offconv_kernel(const float* __restrict__ xin,
                               const float* __restrict__ bias, int which) {
    __shared__ float xs[3*32*68];   // 26112 bytes
    const int tx = threadIdx.x, ty = threadIdx.y;
    const int tid = ty*16 + tx;     // blockDim (16,13) = 208 threads
    const int b = blockIdx.y, h = blockIdx.x;
    const float* src = which ? (const float*)g_attn0 : xin;

    const float* wT = which ? (const float*)g_wT1 : (const float*)g_wT0;
    const int OPAD = which ? 100 : 52;
    const int O    = which ? 98  : 50;
    float* outp    = which ? (float*)g_off1 : (float*)g_off0;

    int o4 = blockIdx.z * 52 + ty * 4;
    const bool active = (o4 + 4 <= OPAD);
    if (!active) o4 = 0;            // compute harmlessly, never store
    const float* wbase = wT + o4;

    float acc[4][4];
#pragma unroll
    for (int j = 0; j < 4; ++j)
#pragma unroll
        for (int oo = 0; oo < 4; ++oo) acc[j][oo] = 0.f;

    for (int half = 0; half < 2; ++half) {
        __syncthreads();   // protect smem from prior-iteration readers
        for (int i = tid; i < 3*32*64; i += 208) {
            int r = i >> 11, rem = i & 2047, c = rem >> 6, w = rem & 63;
            int hh = h + r - 1;
            float v = 0.f;
            if (hh >= 0 && hh < 64) v = src[((b*64 + (half*32 + c))*64 + hh)*64 + w];
            xs[(r*32 + c)*68 + w + 1] = v;
        }
        for (int i = tid; i < 96; i += 208) {
            int base = i * 68;
            xs[base] = 0.f; xs[base+65] = 0.f; xs[base+66] = 0.f; xs[base+67] = 0.f;
        }
        __syncthreads();

        for (int c = 0; c < 32; ++c) {
            const float* xrow = xs + c*68 + 4*tx;
            const float* wrow = wbase + (half*32 + c)*9*OPAD;
#pragma unroll
            for (int dy = 0; dy < 3; ++dy) {
                float4 A  = *(const float4*)(xrow + dy*(32*68));
                float2 Bv = *(const float2*)(xrow + dy*(32*68) + 4);
                float v[6] = {A.x, A.y, A.z, A.w, Bv.x, Bv.y};
#pragma unroll
                for (int dx = 0; dx < 3; ++dx) {
                    float4 wv = *(const float4*)(wrow + (dy*3 + dx)*OPAD);
#pragma unroll
                    for (int j = 0; j < 4; ++j) {
                        acc[j][0] += v[j+dx] * wv.x;
                        acc[j][1] += v[j+dx] * wv.y;
                        acc[j][2] += v[j+dx] * wv.z;
                        acc[j][3] += v[j+dx] * wv.w;
                    }
                }
            }
        }
    }

    if (active) {
#pragma unroll
        for (int oo = 0; oo < 4; ++oo) {
            int o = o4 + oo;
            if (o >= O) break;
            float bb = bias[o];
            int base = ((b*O + o)*64 + h)*64 + 4*tx;
            outp[base + 0] = acc[0][oo] + bb;
            outp[base + 1] = acc[1][oo] + bb;
            outp[base + 2] = acc[2][oo] + bb;
            outp[base + 3] = acc[3][oo] + bb;
        }
    }
}

// ---------------- deformable depthwise conv ----------------
// One thread per channel (tx), 8 pixels per block (ty). Gathers from NHWC image.
// FUSE=false: src=g_xT, off=g_off0, writes g_attn0 (NCHW) + g_attn0T (NHWC)
// FUSE=true : src=g_attn0T, off=g_off1, then fused 1x1 conv + out = x*attn
template<int K, int DIL, bool FUSE>
__global__ void __launch_bounds__(512) deform_kernel(const float* __restrict__ bdw,
                                                     float* __restrict__ outFinal,
                                                     const float* __restrict__ x,
                                                     const float* __restrict__ bpw) {
    constexpr int K2  = K * K;
    constexpr int PAD = (K / 2) * DIL;
    __shared__ float s_wdw[K2*64];
    __shared__ float s_t[64*9];
    __shared__ float s_a[FUSE ? 8*65 : 1];
    __shared__ float s_pw[FUSE ? 64*64 : 1];

    const int tx = threadIdx.x;          // channel
    const int p  = threadIdx.y;          // pixel in block
    const int tid = p*64 + tx;
    const int b = blockIdx.z, h = blockIdx.y, w0 = blockIdx.x * 8;
    const int w = w0 + p;

    const float* wdwT = FUSE ? (const float*)g_wdw1T : (const float*)g_wdw0T;
    for (int i = tid; i < K2*64; i += 512) s_wdw[i] = wdwT[i];
    if (FUSE) for (int i = tid; i < 4096; i += 512) s_pw[i] = g_wpwT[i];
    __syncthreads();

    const float* offp = (FUSE ? (const float*)g_off1 : (const float*)g_off0)
                        + (b*2*K2)*4096 + h*64 + w;
    const float* srcb = (FUSE ? (const float*)g_attn0T : (const float*)g_xT)
                        + b*4096*64 + tx;

    float acc = 0.f;
    for (int k = 0; k < K2; ++k) {
        float oy = offp[(2*k)   * 4096];
        float ox = offp[(2*k+1) * 4096];
        float py = (float)(h - PAD + DIL * (k / K)) + oy;
        float px = (float)(w - PAD + DIL * (k % K)) + ox;
        float fy = floorf(py), fx = floorf(px);
        float wy1 = py - fy, wx1 = px - fx;
        int y0 = (int)fy, x0 = (int)fx;
        bool yv0 = (unsigned)y0       < 64u;
        bool yv1 = (unsigned)(y0 + 1) < 64u;
        bool xv0 = (unsigned)x0       < 64u;
        bool xv1 = (unsigned)(x0 + 1) < 64u;
        const float* pp0 = srcb + (y0*64 + x0)*64;
        float g00 = (yv0 & xv0) ? pp0[0]    : 0.f;
        float g01 = (yv0 & xv1) ? pp0[64]   : 0.f;
        float g10 = (yv1 & xv0) ? pp0[4096] : 0.f;
        float g11 = (yv1 & xv1) ? pp0[4160] : 0.f;
        float vt = g00 + wx1 * (g01 - g00);
        float vb = g10 + wx1 * (g11 - g10);
        acc += (vt + wy1 * (vb - vt)) * s_wdw[k*64 + tx];
    }
    acc += bdw[tx];

    if (!FUSE) {
        g_attn0T[(b*4096 + h*64 + w)*64 + tx] = acc;
        s_t[tx*9 + p] = acc;
        __syncthreads();
        int cc = tid >> 3, pp2 = tid & 7;
        g_attn0[((b*64 + cc)*64 + h)*64 + w0 + pp2] = s_t[cc*9 + pp2];
    } else {
        s_a[p*65 + tx] = acc;
        __syncthreads();
        float r = bpw[tx];       // thread tx now plays output-channel o
#pragma unroll 8
        for (int c = 0; c < 64; ++c)
            r += s_a[p*65 + c] * s_pw[c*64 + tx];
        s_t[tx*9 + p] = r;
        __syncthreads();
        int cc = tid >> 3, pp2 = tid & 7;
        int gi = ((b*64 + cc)*64 + h)*64 + w0 + pp2;
        outFinal[gi] = x[gi] * s_t[cc*9 + pp2];
    }
}

// ---------------- launch ----------------
extern "C" void kernel_launch(void* const* d_in, const int* in_sizes, int n_in,
                              void* d_out, int out_size) {
    const float* x      = (const float*)d_in[0];
    const float* w_off0 = (const float*)d_in[1];
    const float* b_off0 = (const float*)d_in[2];
    const float* w_dw0  = (const float*)d_in[3];
    const float* b_dw0  = (const float*)d_in[4];
    const float* w_off1 = (const float*)d_in[5];
    const float* b_off1 = (const float*)d_in[6];
    const float* w_dw1  = (const float*)d_in[7];
    const float* b_dw1  = (const float*)d_in[8];
    const float* w_pw   = (const float*)d_in[9];
    const float* b_pw   = (const float*)d_in[10];
    float* out = (float*)d_out;

    prep_kernel<<<(576*100 + 255)/256, 256>>>(w_off0, w_off1, w_dw0, w_dw1, w_pw);
    transpose_kernel<<<NB*64, 256>>>(x);

    dim3 cb(16, 13);
    offconv_kernel<<<dim3(64, NB, 1), cb>>>(x, b_off0, 0);

    deform_kernel<5, 1, false><<<dim3(8, 64, NB), dim3(64, 8)>>>(b_dw0, nullptr, nullptr, nullptr);

    offconv_kernel<<<dim3(64, NB, 2), cb>>>(x, b_off1, 1);

    deform_kernel<7, 3, true><<<dim3(8, 64, NB), dim3(64, 8)>>>(b_dw1, out, x, b_pw);
}

// round 3
// speedup vs baseline: 1.7045x; 1.7045x over previous
#include <cuda_runtime.h>

#define NB 4
#define NC 64
#define NH 64
#define NW 64
#define NHW 4096

// ---------------- device scratch ----------------
__device__ __align__(16) float g_xT[NB*NHW*NC];      // x in NHWC
__device__ __align__(16) float g_attn0[NB*NC*NHW];   // attn after deform0, NCHW
__device__ __align__(16) float g_attn0T[NB*NHW*NC];  // attn after deform0, NHWC
__device__ __align__(16) float g_off0 [NB*50*NHW];   // partial (c 0..31) + bias
__device__ __align__(16) float g_off0b[NB*50*NHW];   // partial (c 32..63)
__device__ __align__(16) float g_off1 [NB*98*NHW];
__device__ __align__(16) float g_off1b[NB*98*NHW];
__device__ __align__(16) float g_wT0[576*52];        // [c*9+tap][o] padded 50->52
__device__ __align__(16) float g_wT1[576*100 + 64];  // padded 98->100 (+guard)
__device__ __align__(16) float g_wdw0T[25*64];       // [k][c]
__device__ __align__(16) float g_wdw1T[49*64];       // [k][c]
__device__ __align__(16) float g_wpwT[64*64];        // [c][o]

// ---------------- weight repack ----------------
__global__ void prep_kernel(const float* __restrict__ w_off0, const float* __restrict__ w_off1,
                            const float* __restrict__ w_dw0,  const float* __restrict__ w_dw1,
                            const float* __restrict__ w_pw) {
    int i = blockIdx.x * 256 + threadIdx.x;
    if (i < 576*52) {
        int r = i / 52, o = i % 52, c = r / 9, t = r % 9;
        g_wT0[i] = (o < 50) ? w_off0[(o*64 + c)*9 + t] : 0.f;
    }
    if (i < 576*100) {
        int r = i / 100, o = i % 100, c = r / 9, t = r % 9;
        g_wT1[i] = (o < 98) ? w_off1[(o*64 + c)*9 + t] : 0.f;
    }
    if (i < 25*64) { int k = i >> 6, c = i & 63; g_wdw0T[i] = w_dw0[c*25 + k]; }
    if (i < 49*64) { int k = i >> 6, c = i & 63; g_wdw1T[i] = w_dw1[c*49 + k]; }
    if (i < 4096)  { int c = i >> 6, o = i & 63; g_wpwT[i]  = w_pw[o*64 + c]; }
}

// ---------------- NCHW -> NHWC transpose of x ----------------
__global__ void transpose_kernel(const float* __restrict__ x) {
    __shared__ float sm[64*65];
    int bh = blockIdx.x;
    int b = bh >> 6, h = bh & 63;
    int tid = threadIdx.x;
    for (int i = tid; i < 4096; i += 256) {
        int c = i >> 6, w = i & 63;
        sm[c*65 + w] = x[((b*64 + c)*64 + h)*64 + w];
    }
    __syncthreads();
    for (int i = tid; i < 4096; i += 256) {
        int w = i >> 6, c = i & 63;
        g_xT[(b*4096 + h*64 + w)*64 + c] = sm[c*65 + w];
    }
}

// ---------------- 3x3 offset conv (pad=1), split-C partials ----------------
// Each block: one (b,h), one 32-channel half, one 52-wide o-group.
// half==0 writes base buffer (+bias); half==1 writes the 'b' buffer (no bias).
__global__ void offconv_kernel(const float* __restrict__ xin,
                               const float* __restrict__ bias, int which) {
    __shared__ float xs[3*32*68];   // 26112 bytes
    const int tx = threadIdx.x, ty = threadIdx.y;
    const int tid = ty*16 + tx;     // blockDim (16,13) = 208 threads
    const int b = blockIdx.y, h = blockIdx.x;
    const int half = blockIdx.z & 1;
    const int ogrp = blockIdx.z >> 1;
    const float* src = which ? (const float*)g_attn0 : xin;

    const float* wT = which ? (const float*)g_wT1 : (const float*)g_wT0;
    const int OPAD = which ? 100 : 52;
    const int O    = which ? 98  : 50;
    float* outp;
    if (which) outp = half ? (float*)g_off1b : (float*)g_off1;
    else       outp = half ? (float*)g_off0b : (float*)g_off0;

    int o4 = ogrp*52 + ty*4;
    const bool active = (o4 + 4 <= OPAD);
    if (!active) o4 = 0;
    const float* wbase = wT + o4;

    // load this half's channels: rows h-1..h+1
    for (int i = tid; i < 3*32*64; i += 208) {
        int r = i >> 11, rem = i & 2047, c = rem >> 6, w = rem & 63;
        int hh = h + r - 1;
        float v = 0.f;
        if (hh >= 0 && hh < 64) v = src[((b*64 + (half*32 + c))*64 + hh)*64 + w];
        xs[(r*32 + c)*68 + w + 1] = v;
    }
    for (int i = tid; i < 96; i += 208) {
        int base = i * 68;
        xs[base] = 0.f; xs[base+65] = 0.f; xs[base+66] = 0.f; xs[base+67] = 0.f;
    }
    __syncthreads();

    float acc[4][4];
#pragma unroll
    for (int j = 0; j < 4; ++j)
#pragma unroll
        for (int oo = 0; oo < 4; ++oo) acc[j][oo] = 0.f;

    for (int c = 0; c < 32; ++c) {
        const float* xrow = xs + c*68 + 4*tx;
        const float* wrow = wbase + (half*32 + c)*9*OPAD;
#pragma unroll
        for (int dy = 0; dy < 3; ++dy) {
            float4 A  = *(const float4*)(xrow + dy*(32*68));
            float2 Bv = *(const float2*)(xrow + dy*(32*68) + 4);
            float v[6] = {A.x, A.y, A.z, A.w, Bv.x, Bv.y};
#pragma unroll
            for (int dx = 0; dx < 3; ++dx) {
                float4 wv = *(const float4*)(wrow + (dy*3 + dx)*OPAD);
#pragma unroll
                for (int j = 0; j < 4; ++j) {
                    acc[j][0] += v[j+dx] * wv.x;
                    acc[j][1] += v[j+dx] * wv.y;
                    acc[j][2] += v[j+dx] * wv.z;
                    acc[j][3] += v[j+dx] * wv.w;
                }
            }
        }
    }

    if (active) {
#pragma unroll
        for (int oo = 0; oo < 4; ++oo) {
            int o = o4 + oo;
            if (o >= O) break;
            float bb = half ? 0.f : bias[o];
            int base = ((b*O + o)*64 + h)*64 + 4*tx;
            outp[base + 0] = acc[0][oo] + bb;
            outp[base + 1] = acc[1][oo] + bb;
            outp[base + 2] = acc[2][oo] + bb;
            outp[base + 3] = acc[3][oo] + bb;
        }
    }
}

// ---------------- deformable depthwise conv, shared tap precompute ----------------
// Block: 16 pixels (one quarter of a row) x 64 channels. threads (32,16):
// tx = channel pair (2 channels via float2), p = pixel.
// Stage 1: 512 threads cooperatively precompute, per (pixel,tap):
//          4 clamped gather indices (int4) + 4 validity-masked bilinear weights (float4).
// Stage 2: channel threads do pure gather+FMA.
template<int K, int DIL, bool FUSE>
__global__ void __launch_bounds__(512) deform_kernel(const float* __restrict__ bdw,
                                                     float* __restrict__ outF,
                                                     const float* __restrict__ x,
                                                     const float* __restrict__ bpw) {
    constexpr int K2  = K * K;
    constexpr int PAD = (K / 2) * DIL;
    constexpr int E   = K2 * 16;
    __shared__ int4   s_i4[E];
    __shared__ float4 s_w4[E];
    __shared__ float  s_wdw[K2*64];

    const int tx = threadIdx.x;          // channel pair: channels 2tx, 2tx+1
    const int p  = threadIdx.y;          // pixel within block
    const int tid = p*32 + tx;
    const int b = blockIdx.z, h = blockIdx.y, w0 = blockIdx.x * 16;

    // depthwise weights -> smem
    const float* wdwT = FUSE ? (const float*)g_wdw1T : (const float*)g_wdw0T;
    for (int i = tid; i < K2*64; i += 512) s_wdw[i] = wdwT[i];

    // ---- stage 1: per (pixel, tap) sampling params ----
    const float* offA = (FUSE ? (const float*)g_off1  : (const float*)g_off0 )
                        + (size_t)(b*2*K2)*4096 + h*64 + w0;
    const float* offB = (FUSE ? (const float*)g_off1b : (const float*)g_off0b)
                        + (size_t)(b*2*K2)*4096 + h*64 + w0;
    for (int e = tid; e < E; e += 512) {
        int k = e >> 4, pp = e & 15;
        float oy = offA[(2*k)*4096   + pp] + offB[(2*k)*4096   + pp];
        float ox = offA[(2*k+1)*4096 + pp] + offB[(2*k+1)*4096 + pp];
        float py = (float)(h - PAD + DIL*(k/K)) + oy;
        float px = (float)(w0 + pp - PAD + DIL*(k%K)) + ox;
        float fy = floorf(py), fx = floorf(px);
        float wy1 = py - fy, wx1 = px - fx;
        int y0 = (int)fy, x0i = (int)fx;
        bool yv0 = (unsigned)y0        < 64u;
        bool yv1 = (unsigned)(y0 + 1)  < 64u;
        bool xv0 = (unsigned)x0i       < 64u;
        bool xv1 = (unsigned)(x0i + 1) < 64u;
        int yc0 = min(max(y0, 0), 63),     yc1 = min(max(y0 + 1, 0), 63);
        int xc0 = min(max(x0i, 0), 63),    xc1 = min(max(x0i + 1, 0), 63);
        float wy0f = 1.f - wy1, wx0f = 1.f - wx1;
        s_i4[e] = make_int4(yc0*4096 + xc0*64, yc0*4096 + xc1*64,
                            yc1*4096 + xc0*64, yc1*4096 + xc1*64);
        s_w4[e] = make_float4((yv0 && xv0) ? wy0f*wx0f : 0.f,
                              (yv0 && xv1) ? wy0f*wx1  : 0.f,
                              (yv1 && xv0) ? wy1 *wx0f : 0.f,
                              (yv1 && xv1) ? wy1 *wx1  : 0.f);
    }
    __syncthreads();

    // ---- stage 2: gather + depthwise accumulate (2 channels/thread) ----
    const float* base = (FUSE ? (const float*)g_attn0T : (const float*)g_xT)
                        + (size_t)b*262144 + 2*tx;
    float accx = 0.f, accy = 0.f;
#pragma unroll 7
    for (int k = 0; k < K2; ++k) {
        int e = (k << 4) | p;
        int4   I  = s_i4[e];
        float4 Wt = s_w4[e];
        float2 g00 = *(const float2*)(base + I.x);
        float2 g01 = *(const float2*)(base + I.y);
        float2 g10 = *(const float2*)(base + I.z);
        float2 g11 = *(const float2*)(base + I.w);
        float2 wd  = *(const float2*)(s_wdw + k*64 + 2*tx);
        float vx = g00.x*Wt.x + g01.x*Wt.y + g10.x*Wt.z + g11.x*Wt.w;
        float vy = g00.y*Wt.x + g01.y*Wt.y + g10.y*Wt.z + g11.y*Wt.w;
        accx += vx * wd.x;
        accy += vy * wd.y;
    }
    float2 bd = *(const float2*)(bdw + 2*tx);
    accx += bd.x; accy += bd.y;

    if (!FUSE) {
        // NHWC out (direct, coalesced)
        float2 av; av.x = accx; av.y = accy;
        *(float2*)(g_attn0T + (size_t)(b*4096 + h*64 + w0 + p)*64 + 2*tx) = av;
        // NCHW out via smem transpose (alias s_w4 — done reading it)
        __syncthreads();
        float* s_t = (float*)s_w4;           // [p][c] stride 68
        s_t[p*68 + 2*tx]     = accx;
        s_t[p*68 + 2*tx + 1] = accy;
        __syncthreads();
        for (int v = tid; v < 1024; v += 512) {
            int c = v >> 4, pp = v & 15;
            g_attn0[((b*64 + c)*64 + h)*64 + w0 + pp] = s_t[pp*68 + c];
        }
    } else {
        // fused 1x1 conv + out = x * attn
        __syncthreads();
        float* s_a = (float*)s_i4;           // [p][c] stride 68
        s_a[p*68 + 2*tx]     = accx;
        s_a[p*68 + 2*tx + 1] = accy;
        __syncthreads();
        float2 bp = *(const float2*)(bpw + 2*tx);
        float rx = bp.x, ry = bp.y;
        const float* pwp = (const float*)g_wpwT + 2*tx;
#pragma unroll 8
        for (int c = 0; c < 64; ++c) {
            float a = s_a[p*68 + c];
            float2 pwv = *(const float2*)(pwp + c*64);
            rx += a * pwv.x;
            ry += a * pwv.y;
        }
        float* s_t = (float*)s_w4;           // [p][o] stride 68
        s_t[p*68 + 2*tx]     = rx;
        s_t[p*68 + 2*tx + 1] = ry;
        __syncthreads();
        for (int v = tid; v < 1024; v += 512) {
            int c = v >> 4, pp = v & 15;
            int gi = ((b*64 + c)*64 + h)*64 + w0 + pp;
            outF[gi] = x[gi] * s_t[pp*68 + c];
        }
    }
}

// ---------------- launch ----------------
extern "C" void kernel_launch(void* const* d_in, const int* in_sizes, int n_in,
                              void* d_out, int out_size) {
    const float* x      = (const float*)d_in[0];
    const float* w_off0 = (const float*)d_in[1];
    const float* b_off0 = (const float*)d_in[2];
    const float* w_dw0  = (const float*)d_in[3];
    const float* b_dw0  = (const float*)d_in[4];
    const float* w_off1 = (const float*)d_in[5];
    const float* b_off1 = (const float*)d_in[6];
    const float* w_dw1  = (const float*)d_in[7];
    const float* b_dw1  = (const float*)d_in[8];
    const float* w_pw   = (const float*)d_in[9];
    const float* b_pw   = (const float*)d_in[10];
    float* out = (float*)d_out;

    prep_kernel<<<(576*100 + 255)/256, 256>>>(w_off0, w_off1, w_dw0, w_dw1, w_pw);
    transpose_kernel<<<NB*64, 256>>>(x);

    dim3 cb(16, 13);
    offconv_kernel<<<dim3(64, NB, 2), cb>>>(x, b_off0, 0);

    deform_kernel<5, 1, false><<<dim3(4, 64, NB), dim3(32, 16)>>>(b_dw0, nullptr, nullptr, nullptr);

    offconv_kernel<<<dim3(64, NB, 4), cb>>>(x, b_off1, 1);

    deform_kernel<7, 3, true><<<dim3(4, 64, NB), dim3(32, 16)>>>(b_dw1, out, x, b_pw);
}